// round 9
// baseline (speedup 1.0000x reference)
#include <cuda_runtime.h>
#include <cuda_bf16.h>
#include <cstdint>

#define BB 2
#define NN 8192
#define KK 16
#define CIN 64
#define COUT 128
#define NPTS (BB*NN)

__device__ float g_q[NPTS * COUT];
__device__ float g_k[NPTS * COUT];
__device__ float g_v[NPTS * COUT];
// 3 stages x (K'=384 x N=128) bf16, packed in m16n8k16 B-fragment order
__device__ __align__(16) uint16_t g_Bpk[3 * 49152];

// ---------------- mma.sync helpers (family-common PTX, works on compute_103) ----
__device__ __forceinline__ void mma16816(float* c, uint32_t a0, uint32_t a1,
                                         uint32_t a2, uint32_t a3,
                                         uint32_t b0, uint32_t b1) {
    asm volatile(
        "mma.sync.aligned.m16n8k16.row.col.f32.bf16.bf16.f32 "
        "{%0,%1,%2,%3}, {%4,%5,%6,%7}, {%8,%9}, {%0,%1,%2,%3};"
        : "+f"(c[0]), "+f"(c[1]), "+f"(c[2]), "+f"(c[3])
        : "r"(a0), "r"(a1), "r"(a2), "r"(a3), "r"(b0), "r"(b1));
}

// one 128-col region (8 k-steps of k16) against N=128 (16 n-tiles)
__device__ __forceinline__ void mma_region(float acc[64], const uint32_t A[32], const uint4* B) {
    #pragma unroll
    for (int kkm = 0; kkm < 8; ++kkm) {
        #pragma unroll
        for (int p = 0; p < 8; ++p) {
            uint4 bb = B[kkm * 256 + p * 32];   // 2 n-tiles' fragments per LDG.128
            mma16816(acc + 8*p,     A[4*kkm], A[4*kkm+1], A[4*kkm+2], A[4*kkm+3], bb.x, bb.y);
            mma16816(acc + 8*p + 4, A[4*kkm], A[4*kkm+1], A[4*kkm+2], A[4*kkm+3], bb.z, bb.w);
        }
    }
}

// full stage: K' = [hi | lo | hi] x B' = [Whi | Whi | Wlo]
__device__ __forceinline__ void mma_stage(float acc[64], const uint32_t Ahi[32],
                                          const uint32_t Alo[32], int stage, int lane) {
    const uint4* B = reinterpret_cast<const uint4*>(g_Bpk + stage * 49152) + lane;
    mma_region(acc, Ahi, B);
    mma_region(acc, Alo, B + 2048);
    mma_region(acc, Ahi, B + 4096);
}

// C-fragment (fp32, 64 vals) -> A-fragment hi/lo (bf16x2 packed)
__device__ __forceinline__ void build_A(const float* v, uint32_t* Ahi, uint32_t* Alo) {
    #pragma unroll
    for (int i = 0; i < 32; ++i) {
        int vi = (i >> 1) * 4 + (i & 1) * 2;
        float v0 = v[vi], v1 = v[vi + 1];
        uint32_t u0 = __float_as_uint(v0), u1 = __float_as_uint(v1);
        Ahi[i] = __byte_perm(u0, u1, 0x7632);            // truncated-bf16 pair
        float l0 = v0 - __uint_as_float(u0 & 0xFFFF0000u);
        float l1 = v1 - __uint_as_float(u1 & 0xFFFF0000u);
        asm("cvt.rn.bf16x2.f32 %0, %1, %2;" : "=r"(Alo[i]) : "f"(l1), "f"(l0));
    }
}

__device__ __forceinline__ void init_bias(float acc[64], const float* __restrict__ bias, int c2) {
    #pragma unroll
    for (int j = 0; j < 16; ++j) {
        float2 b2 = *reinterpret_cast<const float2*>(bias + 8*j + c2);
        acc[4*j+0] = b2.x; acc[4*j+1] = b2.y; acc[4*j+2] = b2.x; acc[4*j+3] = b2.y;
    }
}

// ---------------- kernel 0: pack stage weights into B-fragment layout ----------
__global__ void __launch_bounds__(256) pack_w_kernel(
    const float* __restrict__ Wp2, const float* __restrict__ Wa1, const float* __restrict__ Wa2)
{
    int t = blockIdx.x * 256 + threadIdx.x;       // < 147456
    int s = t / 49152, e = t % 49152;
    int kp = e >> 7, n = e & 127;
    const float* W = (s == 0) ? Wp2 : (s == 1) ? Wa1 : Wa2;
    int korig = (kp < 128) ? kp : (kp < 256 ? kp - 128 : kp - 256);
    float w = W[korig * 128 + n];
    uint32_t wu = __float_as_uint(w);
    uint16_t val;
    if (kp < 256) val = (uint16_t)(wu >> 16);     // hi (truncated bf16)
    else {
        float lo = w - __uint_as_float(wu & 0xFFFF0000u);
        val = __bfloat16_as_ushort(__float2bfloat16(lo));
    }
    int kk = kp >> 4, row = kp & 15;
    int reg = row >> 3, half = row & 1, l = ((n & 7) << 2) | ((row >> 1) & 3);
    int p = n >> 4, jo = (n >> 3) & 1;
    int byteoff = kk * 4096 + p * 512 + l * 16 + jo * 8 + reg * 4 + half * 2;
    g_Bpk[s * 49152 + (byteoff >> 1)] = val;
}

// ---------------- kernel 1: q/k/v projections (unchanged, proven) --------------
__global__ void __launch_bounds__(128) proj_kernel(
    const float* __restrict__ x,
    const float* __restrict__ Wq,  const float* __restrict__ bq,
    const float* __restrict__ Wkv, const float* __restrict__ bkv)
{
    __shared__ float s_x[16][64];
    const int tid = threadIdx.x, row0 = blockIdx.x * 16, g = blockIdx.y;
    for (int i = tid; i < 256; i += 128) {
        int r = i >> 4, c4 = i & 15;
        reinterpret_cast<float4*>(&s_x[r][0])[c4] =
            reinterpret_cast<const float4*>(x + (size_t)(row0 + r) * CIN)[c4];
    }
    __syncthreads();
    const int rt = tid >> 5, l = tid & 31;
    const float* W; const float* bias; float* out; int ldw, cb;
    if (g == 0)      { W = Wq;  ldw = 128; cb = 0;   bias = bq;        out = g_q; }
    else if (g == 1) { W = Wkv; ldw = 256; cb = 0;   bias = bkv;       out = g_k; }
    else             { W = Wkv; ldw = 256; cb = 128; bias = bkv + 128; out = g_v; }
    float4 acc[4];
    #pragma unroll
    for (int r = 0; r < 4; ++r) acc[r] = make_float4(0.f, 0.f, 0.f, 0.f);
    const float* wp = W + cb + 4 * l;
    #pragma unroll 4
    for (int k = 0; k < CIN; ++k) {
        float4 w = *reinterpret_cast<const float4*>(wp + (size_t)k * ldw);
        #pragma unroll
        for (int r = 0; r < 4; ++r) {
            float a = s_x[rt * 4 + r][k];
            acc[r].x = fmaf(a, w.x, acc[r].x); acc[r].y = fmaf(a, w.y, acc[r].y);
            acc[r].z = fmaf(a, w.z, acc[r].z); acc[r].w = fmaf(a, w.w, acc[r].w);
        }
    }
    float4 bv = *reinterpret_cast<const float4*>(bias + 4 * l);
    #pragma unroll
    for (int r = 0; r < 4; ++r) {
        float4 o = acc[r];
        o.x += bv.x; o.y += bv.y; o.z += bv.z; o.w += bv.w;
        *reinterpret_cast<float4*>(out + (size_t)(row0 + rt * 4 + r) * COUT + 4 * l) = o;
    }
}

// ---------------- kernel 2: fused attention, 1 warp = 1 point, HMMA stages -----
__global__ void __launch_bounds__(256) attn_kernel(
    const float* __restrict__ pos, const int* __restrict__ idx,
    const float* __restrict__ Wp1, const float* __restrict__ bp1,
    const float* __restrict__ bp2, const float* __restrict__ ba1,
    const float* __restrict__ ba2,
    const float* __restrict__ Wo,  const float* __restrict__ bo,
    float* __restrict__ out)
{
    extern __shared__ float smf[];
    float* sPE  = smf;                   // 8 warps x 16 rows x stride 132 = 16896 f
    float* sAgg = smf + 16896;           // 8 x 128
    float* sW1  = smf + 17920;           // Wp1(384) + bp1(128)
    int*   sIdx = (int*)(smf + 18432);   // 128

    const int tid = threadIdx.x, w = tid >> 5, lane = tid & 31;
    const int g = lane >> 2, c2 = (lane & 3) * 2;
    const int p0 = blockIdx.x * 8;
    const int bbase = (p0 / NN) * NN;

    if (tid < 128) sIdx[tid] = idx[p0 * KK + tid];
    for (int i = tid; i < 512; i += 256) sW1[i] = (i < 384) ? Wp1[i] : bp1[i - 384];
    __syncthreads();

    const int i0 = sIdx[w * 16 + g], i1 = sIdx[w * 16 + g + 8];

    float acc[64];
    uint32_t Ahi[32], Alo[32];

    // stage 1 (scalar): hidden = relu(pos_diff @ Wp1 + bp1), straight into fragments
    {
        const float* pp  = pos + (size_t)(p0 + w) * 3;
        const float* pn0 = pos + (size_t)(bbase + i0) * 3;
        const float* pn1 = pos + (size_t)(bbase + i1) * 3;
        float px = pp[0], py = pp[1], pz = pp[2];
        float ax = px - pn0[0], ay = py - pn0[1], az = pz - pn0[2];
        float bx = px - pn1[0], by = py - pn1[1], bz = pz - pn1[2];
        #pragma unroll
        for (int j = 0; j < 16; ++j)
            #pragma unroll
            for (int q = 0; q < 2; ++q) {
                int cc = 8 * j + c2 + q;
                float w0 = sW1[cc], w1 = sW1[128 + cc], w2 = sW1[256 + cc], bb = sW1[384 + cc];
                acc[4*j + q]     = fmaxf(fmaf(ax, w0, fmaf(ay, w1, fmaf(az, w2, bb))), 0.f);
                acc[4*j + 2 + q] = fmaxf(fmaf(bx, w0, fmaf(by, w1, fmaf(bz, w2, bb))), 0.f);
            }
    }
    build_A(acc, Ahi, Alo);

    // stage 2 (HMMA): pos_enc = hidden @ Wp2 + bp2
    init_bias(acc, bp2, c2);
    mma_stage(acc, Ahi, Alo, 0, lane);

    // spill PE (thread-private smem) and form rel = k_n - q + PE in place
    float* pe0 = sPE + w * 2112 + g * 132;
    float* pe1 = pe0 + 8 * 132;
    {
        const float* kr0 = g_k + (size_t)(bbase + i0) * COUT;
        const float* kr1 = g_k + (size_t)(bbase + i1) * COUT;
        const float* qr  = g_q + (size_t)(p0 + w) * COUT;
        #pragma unroll
        for (int j = 0; j < 16; ++j) {
            int cc = 8 * j + c2;
            *reinterpret_cast<float2*>(pe0 + cc) = make_float2(acc[4*j],     acc[4*j + 1]);
            *reinterpret_cast<float2*>(pe1 + cc) = make_float2(acc[4*j + 2], acc[4*j + 3]);
            float2 q2 = *reinterpret_cast<const float2*>(qr  + cc);
            float2 k0 = *reinterpret_cast<const float2*>(kr0 + cc);
            float2 k1 = *reinterpret_cast<const float2*>(kr1 + cc);
            acc[4*j]     += k0.x - q2.x;  acc[4*j + 1] += k0.y - q2.y;
            acc[4*j + 2] += k1.x - q2.x;  acc[4*j + 3] += k1.y - q2.y;
        }
    }
    build_A(acc, Ahi, Alo);

    // stage 3 (HMMA): mid = relu(rel @ Wa1 + ba1)
    init_bias(acc, ba1, c2);
    mma_stage(acc, Ahi, Alo, 1, lane);
    #pragma unroll
    for (int i = 0; i < 64; ++i) acc[i] = fmaxf(acc[i], 0.f);
    build_A(acc, Ahi, Alo);

    // stage 4 (HMMA): logits = mid @ Wa2 + ba2
    init_bias(acc, ba2, c2);
    mma_stage(acc, Ahi, Alo, 2, lane);

    // softmax over K (the 16 m-rows) per channel + aggregate with (v_n + PE)
    {
        const float* vr0 = g_v + (size_t)(bbase + i0) * COUT;
        const float* vr1 = g_v + (size_t)(bbase + i1) * COUT;
        #pragma unroll
        for (int j = 0; j < 16; ++j) {
            int cc = 8 * j + c2;
            float m0 = fmaxf(acc[4*j],     acc[4*j + 2]);
            float m1 = fmaxf(acc[4*j + 1], acc[4*j + 3]);
            #pragma unroll
            for (int msk = 4; msk <= 16; msk <<= 1) {
                m0 = fmaxf(m0, __shfl_xor_sync(0xFFFFFFFFu, m0, msk));
                m1 = fmaxf(m1, __shfl_xor_sync(0xFFFFFFFFu, m1, msk));
            }
            float e00 = __expf(acc[4*j]     - m0);
            float e01 = __expf(acc[4*j + 2] - m0);
            float e10 = __expf(acc[4*j + 1] - m1);
            float e11 = __expf(acc[4*j + 3] - m1);
            float2 v0 = *reinterpret_cast<const float2*>(vr0 + cc);
            float2 v1 = *reinterpret_cast<const float2*>(vr1 + cc);
            float2 pA = *reinterpret_cast<const float2*>(pe0 + cc);
            float2 pB = *reinterpret_cast<const float2*>(pe1 + cc);
            float num0 = e00 * (v0.x + pA.x) + e01 * (v1.x + pB.x);
            float num1 = e10 * (v0.y + pA.y) + e11 * (v1.y + pB.y);
            float den0 = e00 + e01, den1 = e10 + e11;
            #pragma unroll
            for (int msk = 4; msk <= 16; msk <<= 1) {
                num0 += __shfl_xor_sync(0xFFFFFFFFu, num0, msk);
                num1 += __shfl_xor_sync(0xFFFFFFFFu, num1, msk);
                den0 += __shfl_xor_sync(0xFFFFFFFFu, den0, msk);
                den1 += __shfl_xor_sync(0xFFFFFFFFu, den1, msk);
            }
            if (g == 0) {
                sAgg[w * 128 + cc]     = num0 / den0;
                sAgg[w * 128 + cc + 1] = num1 / den1;
            }
        }
    }
    __syncwarp();

    // Wo projection: per warp GEMV, Wo rows L1-hot
    {
        const int c4 = 4 * lane;
        float4 o = *reinterpret_cast<const float4*>(bo + c4);
        const float* ag = sAgg + w * 128;
        #pragma unroll 8
        for (int k = 0; k < 128; ++k) {
            float a = ag[k];
            float4 wv = *reinterpret_cast<const float4*>(Wo + (size_t)k * 128 + c4);
            o.x = fmaf(a, wv.x, o.x); o.y = fmaf(a, wv.y, o.y);
            o.z = fmaf(a, wv.z, o.z); o.w = fmaf(a, wv.w, o.w);
        }
        *reinterpret_cast<float4*>(out + (size_t)(p0 + w) * COUT + c4) = o;
    }
}

// ---------------------------------------------------------------------------
extern "C" void kernel_launch(void* const* d_in, const int* in_sizes, int n_in,
                              void* d_out, int out_size)
{
    const float* x   = (const float*)d_in[0];
    const float* pos = (const float*)d_in[1];
    const int*   idx = (const int*)  d_in[2];
    const float* Wq  = (const float*)d_in[3];
    const float* bq  = (const float*)d_in[4];
    const float* Wkv = (const float*)d_in[5];
    const float* bkv = (const float*)d_in[6];
    const float* Wp1 = (const float*)d_in[7];
    const float* bp1 = (const float*)d_in[8];
    const float* Wp2 = (const float*)d_in[9];
    const float* bp2 = (const float*)d_in[10];
    const float* Wa1 = (const float*)d_in[11];
    const float* ba1 = (const float*)d_in[12];
    const float* Wa2 = (const float*)d_in[13];
    const float* ba2 = (const float*)d_in[14];
    const float* Wo  = (const float*)d_in[15];
    const float* bo  = (const float*)d_in[16];
    float* out = (float*)d_out;

    const int smem_bytes = 18560 * 4;   // 74240 B
    cudaFuncSetAttribute(attn_kernel, cudaFuncAttributeMaxDynamicSharedMemorySize, smem_bytes);

    pack_w_kernel<<<576, 256>>>(Wp2, Wa1, Wa2);
    dim3 g1(NPTS / 16, 3);
    proj_kernel<<<g1, 128>>>(x, Wq, bq, Wkv, bkv);
    attn_kernel<<<NPTS / 8, 256, smem_bytes>>>(pos, idx, Wp1, bp1, bp2, ba1, ba2, Wo, bo, out);
}

// round 10
// speedup vs baseline: 2.6432x; 2.6432x over previous
#include <cuda_runtime.h>
#include <cuda_bf16.h>
#include <cstdint>

#define BB 2
#define NN 8192
#define KK 16
#define CIN 64
#define COUT 128
#define NPTS (BB*NN)

// smem layout (bytes)
#define OFF_B0   0          // weight region buffer 0 (32 KB)
#define OFF_B1   32768      // weight region buffer 1 (32 KB)
#define OFF_PE   65536      // 8 warps x 16 rows x stride 132 fp32 (67584 B)
#define OFF_AGG  133120     // 8 x 128 fp32
#define OFF_W1   137216     // Wp1(384)+bp1(128) fp32
#define OFF_IDX  139264     // 128 int
#define SMEM_TOTAL 139776

__device__ float g_q[NPTS * COUT];
__device__ float g_k[NPTS * COUT];
__device__ float g_v[NPTS * COUT];
// 3 stages x 2 regions (hi, lo) x (K=128 x N=128) bf16 in m16n8k16 B-fragment order
__device__ __align__(16) uint16_t g_Bpk[3 * 2 * 16384];

// ---------------- mma.sync helpers (family-common, compiles at compute_103) ----
__device__ __forceinline__ void mma16816(float* c, uint32_t a0, uint32_t a1,
                                         uint32_t a2, uint32_t a3,
                                         uint32_t b0, uint32_t b1) {
    asm volatile(
        "mma.sync.aligned.m16n8k16.row.col.f32.bf16.bf16.f32 "
        "{%0,%1,%2,%3}, {%4,%5,%6,%7}, {%8,%9}, {%0,%1,%2,%3};"
        : "+f"(c[0]), "+f"(c[1]), "+f"(c[2]), "+f"(c[3])
        : "r"(a0), "r"(a1), "r"(a2), "r"(a3), "r"(b0), "r"(b1));
}

// one pass: K=128 region (8 k16 chunks) x N=128 (16 n-tiles), B from SMEM
__device__ __forceinline__ void mma_pass(float acc[64], const uint32_t A[32],
                                         const uint4* __restrict__ sB, int lane) {
    const uint4* B = sB + lane;
    #pragma unroll
    for (int kkm = 0; kkm < 8; ++kkm) {
        #pragma unroll
        for (int p = 0; p < 8; ++p) {
            uint4 bb = B[kkm * 256 + p * 32];   // LDS.128: 2 n-tiles' fragments
            mma16816(acc + 8*p,     A[4*kkm], A[4*kkm+1], A[4*kkm+2], A[4*kkm+3], bb.x, bb.y);
            mma16816(acc + 8*p + 4, A[4*kkm], A[4*kkm+1], A[4*kkm+2], A[4*kkm+3], bb.z, bb.w);
        }
    }
}

// C-fragment (fp32 x64) -> A-fragment hi/lo (bf16x2), truncation split
__device__ __forceinline__ void build_A(const float* v, uint32_t* Ahi, uint32_t* Alo) {
    #pragma unroll
    for (int i = 0; i < 32; ++i) {
        int vi = (i >> 1) * 4 + (i & 1) * 2;
        float v0 = v[vi], v1 = v[vi + 1];
        uint32_t u0 = __float_as_uint(v0), u1 = __float_as_uint(v1);
        Ahi[i] = __byte_perm(u0, u1, 0x7632);
        float l0 = v0 - __uint_as_float(u0 & 0xFFFF0000u);
        float l1 = v1 - __uint_as_float(u1 & 0xFFFF0000u);
        asm("cvt.rn.bf16x2.f32 %0, %1, %2;" : "=r"(Alo[i]) : "f"(l1), "f"(l0));
    }
}

__device__ __forceinline__ void init_bias(float acc[64], const float* __restrict__ bias, int c2) {
    #pragma unroll
    for (int j = 0; j < 16; ++j) {
        float2 b2 = *reinterpret_cast<const float2*>(bias + 8*j + c2);
        acc[4*j+0] = b2.x; acc[4*j+1] = b2.y; acc[4*j+2] = b2.x; acc[4*j+3] = b2.y;
    }
}

// cooperative 32 KB region prefetch, gmem -> smem, async
__device__ __forceinline__ void prefetch_region(char* sbuf, const uint16_t* __restrict__ gsrc,
                                                int tid) {
    uint32_t sa = (uint32_t)__cvta_generic_to_shared(sbuf) + tid * 16;
    const char* gp = (const char*)gsrc + tid * 16;
    #pragma unroll
    for (int i = 0; i < 8; ++i)
        asm volatile("cp.async.cg.shared.global [%0], [%1], 16;"
                     :: "r"(sa + i * 4096), "l"(gp + i * 4096));
    asm volatile("cp.async.commit_group;" ::: "memory");
}
#define CP_WAIT_ALL() asm volatile("cp.async.wait_group 0;" ::: "memory")

// ---------------- kernel 0: pack weights into per-region B-fragment layout ----
__global__ void __launch_bounds__(256) pack_w_kernel(
    const float* __restrict__ Wp2, const float* __restrict__ Wa1, const float* __restrict__ Wa2)
{
    int t = blockIdx.x * 256 + threadIdx.x;      // < 98304
    int s = t / 32768, e = t % 32768;
    int r = e >> 14, e2 = e & 16383;
    int kp = e2 >> 7, n = e2 & 127;
    const float* W = (s == 0) ? Wp2 : (s == 1) ? Wa1 : Wa2;
    float w = W[kp * 128 + n];
    uint32_t wu = __float_as_uint(w);
    uint16_t val;
    if (r == 0) val = (uint16_t)(wu >> 16);                       // hi (truncated bf16)
    else {
        float lo = w - __uint_as_float(wu & 0xFFFF0000u);
        val = __bfloat16_as_ushort(__float2bfloat16(lo));         // lo (rounded bf16)
    }
    int kk = kp >> 4, row = kp & 15;
    int reg = row >> 3, half = row & 1, l = ((n & 7) << 2) | ((row >> 1) & 3);
    int p = n >> 4, jo = (n >> 3) & 1;
    int byteoff = kk * 4096 + p * 512 + l * 16 + jo * 8 + reg * 4 + half * 2;
    g_Bpk[(s * 2 + r) * 16384 + (byteoff >> 1)] = val;
}

// ---------------- kernel 1: q/k/v projections (proven) -------------------------
__global__ void __launch_bounds__(128) proj_kernel(
    const float* __restrict__ x,
    const float* __restrict__ Wq,  const float* __restrict__ bq,
    const float* __restrict__ Wkv, const float* __restrict__ bkv)
{
    __shared__ float s_x[16][64];
    const int tid = threadIdx.x, row0 = blockIdx.x * 16, g = blockIdx.y;
    for (int i = tid; i < 256; i += 128) {
        int r = i >> 4, c4 = i & 15;
        reinterpret_cast<float4*>(&s_x[r][0])[c4] =
            reinterpret_cast<const float4*>(x + (size_t)(row0 + r) * CIN)[c4];
    }
    __syncthreads();
    const int rt = tid >> 5, l = tid & 31;
    const float* W; const float* bias; float* out; int ldw, cb;
    if (g == 0)      { W = Wq;  ldw = 128; cb = 0;   bias = bq;        out = g_q; }
    else if (g == 1) { W = Wkv; ldw = 256; cb = 0;   bias = bkv;       out = g_k; }
    else             { W = Wkv; ldw = 256; cb = 128; bias = bkv + 128; out = g_v; }
    float4 acc[4];
    #pragma unroll
    for (int r = 0; r < 4; ++r) acc[r] = make_float4(0.f, 0.f, 0.f, 0.f);
    const float* wp = W + cb + 4 * l;
    #pragma unroll 4
    for (int k = 0; k < CIN; ++k) {
        float4 w = *reinterpret_cast<const float4*>(wp + (size_t)k * ldw);
        #pragma unroll
        for (int r = 0; r < 4; ++r) {
            float a = s_x[rt * 4 + r][k];
            acc[r].x = fmaf(a, w.x, acc[r].x); acc[r].y = fmaf(a, w.y, acc[r].y);
            acc[r].z = fmaf(a, w.z, acc[r].z); acc[r].w = fmaf(a, w.w, acc[r].w);
        }
    }
    float4 bv = *reinterpret_cast<const float4*>(bias + 4 * l);
    #pragma unroll
    for (int r = 0; r < 4; ++r) {
        float4 o = acc[r];
        o.x += bv.x; o.y += bv.y; o.z += bv.z; o.w += bv.w;
        *reinterpret_cast<float4*>(out + (size_t)(row0 + rt * 4 + r) * COUT + 4 * l) = o;
    }
}

// ---------------- kernel 2: fused attention, 1 warp = 1 point, smem-staged B --
__global__ void __launch_bounds__(256, 1) attn_kernel(
    const float* __restrict__ pos, const int* __restrict__ idx,
    const float* __restrict__ Wp1, const float* __restrict__ bp1,
    const float* __restrict__ bp2, const float* __restrict__ ba1,
    const float* __restrict__ ba2,
    const float* __restrict__ Wo,  const float* __restrict__ bo,
    float* __restrict__ out)
{
    extern __shared__ char smem[];
    uint4* sB0  = (uint4*)(smem + OFF_B0);
    uint4* sB1  = (uint4*)(smem + OFF_B1);
    float* sPE  = (float*)(smem + OFF_PE);
    float* sAgg = (float*)(smem + OFF_AGG);
    float* sW1  = (float*)(smem + OFF_W1);
    int*   sIdx = (int*)  (smem + OFF_IDX);

    const int tid = threadIdx.x, w = tid >> 5, lane = tid & 31;
    const int g = lane >> 2, c2 = (lane & 3) * 2;
    const int p0 = blockIdx.x * 8;
    const int bbase = (p0 / NN) * NN;

    prefetch_region(smem + OFF_B0, g_Bpk, tid);          // s0 hi

    if (tid < 128) sIdx[tid] = idx[p0 * KK + tid];
    for (int i = tid; i < 512; i += 256) sW1[i] = (i < 384) ? Wp1[i] : bp1[i - 384];
    __syncthreads();

    const int i0 = sIdx[w * 16 + g], i1 = sIdx[w * 16 + g + 8];

    float acc[64];
    uint32_t Ahi[32], Alo[32];

    // stage 1 (scalar): hidden = relu(pos_diff @ Wp1 + bp1), directly in fragment order
    {
        const float* pp  = pos + (size_t)(p0 + w) * 3;
        const float* pn0 = pos + (size_t)(bbase + i0) * 3;
        const float* pn1 = pos + (size_t)(bbase + i1) * 3;
        float px = pp[0], py = pp[1], pz = pp[2];
        float ax = px - pn0[0], ay = py - pn0[1], az = pz - pn0[2];
        float bx = px - pn1[0], by = py - pn1[1], bz = pz - pn1[2];
        #pragma unroll
        for (int j = 0; j < 16; ++j)
            #pragma unroll
            for (int q = 0; q < 2; ++q) {
                int cc = 8 * j + c2 + q;
                float w0 = sW1[cc], w1 = sW1[128 + cc], w2 = sW1[256 + cc], bb = sW1[384 + cc];
                acc[4*j + q]     = fmaxf(fmaf(ax, w0, fmaf(ay, w1, fmaf(az, w2, bb))), 0.f);
                acc[4*j + 2 + q] = fmaxf(fmaf(bx, w0, fmaf(by, w1, fmaf(bz, w2, bb))), 0.f);
            }
    }
    build_A(acc, Ahi, Alo);

    CP_WAIT_ALL(); __syncthreads();                       // buf0 = s0 hi ready

    // ================= stage 0: pos_enc = hidden @ Wp2 + bp2 =================
    prefetch_region(smem + OFF_B1, g_Bpk + 1 * 16384, tid);   // s0 lo
    init_bias(acc, bp2, c2);
    mma_pass(acc, Ahi, sB0, lane);
    mma_pass(acc, Alo, sB0, lane);
    CP_WAIT_ALL(); __syncthreads();                       // buf1 ready; buf0 free
    prefetch_region(smem + OFF_B0, g_Bpk + 2 * 16384, tid);   // s1 hi
    mma_pass(acc, Ahi, sB1, lane);

    // spill PE, build rel = k_n - q + PE in acc
    float* pe0 = sPE + w * 2112 + g * 132;
    float* pe1 = pe0 + 8 * 132;
    {
        const float* kr0 = g_k + (size_t)(bbase + i0) * COUT;
        const float* kr1 = g_k + (size_t)(bbase + i1) * COUT;
        const float* qr  = g_q + (size_t)(p0 + w) * COUT;
        #pragma unroll
        for (int j = 0; j < 16; ++j) {
            int cc = 8 * j + c2;
            *reinterpret_cast<float2*>(pe0 + cc) = make_float2(acc[4*j],     acc[4*j + 1]);
            *reinterpret_cast<float2*>(pe1 + cc) = make_float2(acc[4*j + 2], acc[4*j + 3]);
            float2 q2 = *reinterpret_cast<const float2*>(qr  + cc);
            float2 k0 = *reinterpret_cast<const float2*>(kr0 + cc);
            float2 k1 = *reinterpret_cast<const float2*>(kr1 + cc);
            acc[4*j]     += k0.x - q2.x;  acc[4*j + 1] += k0.y - q2.y;
            acc[4*j + 2] += k1.x - q2.x;  acc[4*j + 3] += k1.y - q2.y;
        }
    }
    build_A(acc, Ahi, Alo);
    CP_WAIT_ALL(); __syncthreads();                       // buf0 = s1 hi ready

    // ================= stage 1: mid = relu(rel @ Wa1 + ba1) ==================
    prefetch_region(smem + OFF_B1, g_Bpk + 3 * 16384, tid);   // s1 lo
    init_bias(acc, ba1, c2);
    mma_pass(acc, Ahi, sB0, lane);
    mma_pass(acc, Alo, sB0, lane);
    CP_WAIT_ALL(); __syncthreads();
    prefetch_region(smem + OFF_B0, g_Bpk + 4 * 16384, tid);   // s2 hi
    mma_pass(acc, Ahi, sB1, lane);
    #pragma unroll
    for (int i = 0; i < 64; ++i) acc[i] = fmaxf(acc[i], 0.f);
    build_A(acc, Ahi, Alo);
    CP_WAIT_ALL(); __syncthreads();                       // buf0 = s2 hi ready

    // ================= stage 2: logits = mid @ Wa2 + ba2 =====================
    prefetch_region(smem + OFF_B1, g_Bpk + 5 * 16384, tid);   // s2 lo
    init_bias(acc, ba2, c2);
    mma_pass(acc, Ahi, sB0, lane);
    mma_pass(acc, Alo, sB0, lane);
    CP_WAIT_ALL(); __syncthreads();
    mma_pass(acc, Ahi, sB1, lane);

    // softmax over K (16 m-rows) per channel + aggregate with (v_n + PE)
    {
        const float* vr0 = g_v + (size_t)(bbase + i0) * COUT;
        const float* vr1 = g_v + (size_t)(bbase + i1) * COUT;
        #pragma unroll
        for (int j = 0; j < 16; ++j) {
            int cc = 8 * j + c2;
            float m0 = fmaxf(acc[4*j],     acc[4*j + 2]);
            float m1 = fmaxf(acc[4*j + 1], acc[4*j + 3]);
            #pragma unroll
            for (int msk = 4; msk <= 16; msk <<= 1) {
                m0 = fmaxf(m0, __shfl_xor_sync(0xFFFFFFFFu, m0, msk));
                m1 = fmaxf(m1, __shfl_xor_sync(0xFFFFFFFFu, m1, msk));
            }
            float e00 = __expf(acc[4*j]     - m0);
            float e01 = __expf(acc[4*j + 2] - m0);
            float e10 = __expf(acc[4*j + 1] - m1);
            float e11 = __expf(acc[4*j + 3] - m1);
            float2 v0 = *reinterpret_cast<const float2*>(vr0 + cc);
            float2 v1 = *reinterpret_cast<const float2*>(vr1 + cc);
            float2 pA = *reinterpret_cast<const float2*>(pe0 + cc);
            float2 pB = *reinterpret_cast<const float2*>(pe1 + cc);
            float num0 = e00 * (v0.x + pA.x) + e01 * (v1.x + pB.x);
            float num1 = e10 * (v0.y + pA.y) + e11 * (v1.y + pB.y);
            float den0 = e00 + e01, den1 = e10 + e11;
            #pragma unroll
            for (int msk = 4; msk <= 16; msk <<= 1) {
                num0 += __shfl_xor_sync(0xFFFFFFFFu, num0, msk);
                num1 += __shfl_xor_sync(0xFFFFFFFFu, num1, msk);
                den0 += __shfl_xor_sync(0xFFFFFFFFu, den0, msk);
                den1 += __shfl_xor_sync(0xFFFFFFFFu, den1, msk);
            }
            if (g == 0) {
                sAgg[w * 128 + cc]     = num0 / den0;
                sAgg[w * 128 + cc + 1] = num1 / den1;
            }
        }
    }
    __syncthreads();

    // Wo projection: split-K across warps (warp w handles rows w*16..w*16+15), smem reduce
    {
        float* sPart = (float*)(smem + OFF_B0);   // 8 warps x 8 points x 128 cols fp32 = 32 KB
        const int c4 = 4 * lane;
        float4 pacc[8];
        #pragma unroll
        for (int p = 0; p < 8; ++p) pacc[p] = make_float4(0.f, 0.f, 0.f, 0.f);
        #pragma unroll
        for (int kk2 = 0; kk2 < 16; ++kk2) {
            int k = w * 16 + kk2;
            float4 wv = *reinterpret_cast<const float4*>(Wo + (size_t)k * 128 + c4);
            #pragma unroll
            for (int p = 0; p < 8; ++p) {
                float a = sAgg[p * 128 + k];
                pacc[p].x = fmaf(a, wv.x, pacc[p].x);
                pacc[p].y = fmaf(a, wv.y, pacc[p].y);
                pacc[p].z = fmaf(a, wv.z, pacc[p].z);
                pacc[p].w = fmaf(a, wv.w, pacc[p].w);
            }
        }
        #pragma unroll
        for (int p = 0; p < 8; ++p)
            *reinterpret_cast<float4*>(sPart + (size_t)(w * 8 + p) * 128 + c4) = pacc[p];
        __syncthreads();
        #pragma unroll
        for (int i = tid; i < 1024; i += 256) {
            int p = i >> 7, c = i & 127;
            float sum = bo[c];
            #pragma unroll
            for (int ww = 0; ww < 8; ++ww) sum += sPart[(size_t)(ww * 8 + p) * 128 + c];
            out[(size_t)(p0 + p) * COUT + c] = sum;
        }
    }
}

// ---------------------------------------------------------------------------
extern "C" void kernel_launch(void* const* d_in, const int* in_sizes, int n_in,
                              void* d_out, int out_size)
{
    const float* x   = (const float*)d_in[0];
    const float* pos = (const float*)d_in[1];
    const int*   idx = (const int*)  d_in[2];
    const float* Wq  = (const float*)d_in[3];
    const float* bq  = (const float*)d_in[4];
    const float* Wkv = (const float*)d_in[5];
    const float* bkv = (const float*)d_in[6];
    const float* Wp1 = (const float*)d_in[7];
    const float* bp1 = (const float*)d_in[8];
    const float* Wp2 = (const float*)d_in[9];
    const float* bp2 = (const float*)d_in[10];
    const float* Wa1 = (const float*)d_in[11];
    const float* ba1 = (const float*)d_in[12];
    const float* Wa2 = (const float*)d_in[13];
    const float* ba2 = (const float*)d_in[14];
    const float* Wo  = (const float*)d_in[15];
    const float* bo  = (const float*)d_in[16];
    float* out = (float*)d_out;

    cudaFuncSetAttribute(attn_kernel, cudaFuncAttributeMaxDynamicSharedMemorySize, SMEM_TOTAL);

    pack_w_kernel<<<384, 256>>>(Wp2, Wa1, Wa2);
    dim3 g1(NPTS / 16, 3);
    proj_kernel<<<g1, 128>>>(x, Wq, bq, Wkv, bkv);
    attn_kernel<<<NPTS / 8, 256, SMEM_TOTAL>>>(pos, idx, Wp1, bp1, bp2, ba1, ba2, Wo, bo, out);
}